// round 6
// baseline (speedup 1.0000x reference)
#include <cuda_runtime.h>
#include <math.h>

#define BB 128
#define TT 256
#define DD 256
#define NSTK 32
#define ZO 1e-6f

// scratch (no allocations allowed)
__device__ float d_gbuf[BB * TT];
__device__ float d_norms[2];  // [0] = max(||should_pop||, 1e-8), [1] = max(||latch_enable||, 1e-8)

__device__ __forceinline__ float eluf(float v) { return v > 0.f ? v : expm1f(v); }

// ---------------------------------------------------------------------------
// Pass 0: norms of should_pop and latch_enable (single block, 256 threads)
// ---------------------------------------------------------------------------
__global__ void norms_kernel(const float* __restrict__ sp, const float* __restrict__ le) {
    int tid = threadIdx.x;
    float a = sp[tid], b = le[tid];
    float s1 = a * a, s2 = b * b;
#pragma unroll
    for (int o = 16; o; o >>= 1) {
        s1 += __shfl_xor_sync(0xffffffffu, s1, o);
        s2 += __shfl_xor_sync(0xffffffffu, s2, o);
    }
    __shared__ float p1[8], p2[8];
    if ((tid & 31) == 0) { p1[tid >> 5] = s1; p2[tid >> 5] = s2; }
    __syncthreads();
    if (tid == 0) {
        float t1 = 0.f, t2 = 0.f;
#pragma unroll
        for (int w = 0; w < 8; w++) { t1 += p1[w]; t2 += p2[w]; }
        d_norms[0] = fmaxf(sqrtf(t1), 1e-8f);
        d_norms[1] = fmaxf(sqrtf(t2), 1e-8f);
    }
}

// ---------------------------------------------------------------------------
// Pass 1: g[b,t] = elu(cos(latch_enable, x[b,t])) — one warp per (b,t) row
// ---------------------------------------------------------------------------
__global__ void gpass_kernel(const float* __restrict__ x, const float* __restrict__ le) {
    int warp = (blockIdx.x * blockDim.x + threadIdx.x) >> 5;
    int lane = threadIdx.x & 31;
    if (warp >= BB * TT) return;
    const float4* xr = (const float4*)(x + (size_t)warp * DD);
    const float4* lr = (const float4*)le;
    float h1 = 0.f, h2 = 0.f;
#pragma unroll
    for (int i = 0; i < 2; i++) {
        float4 xv = xr[lane * 2 + i];
        float4 lv = lr[lane * 2 + i];
        h1 += xv.x * lv.x + xv.y * lv.y + xv.z * lv.z + xv.w * lv.w;
        h2 += xv.x * xv.x + xv.y * xv.y + xv.z * xv.z + xv.w * xv.w;
    }
#pragma unroll
    for (int o = 16; o; o >>= 1) {
        h1 += __shfl_xor_sync(0xffffffffu, h1, o);
        h2 += __shfl_xor_sync(0xffffffffu, h2, o);
    }
    if (lane == 0) {
        float bn = fmaxf(sqrtf(h2), 1e-8f);
        d_gbuf[warp] = eluf(h1 / (d_norms[1] * bn));
    }
}

// ---------------------------------------------------------------------------
// Pass 2: the sequential scan — one CTA per batch element, thread = D column.
// Stack column lives in registers. Pointer lives in warp-0 lanes.
// Per-step: ONE __syncthreads, double-buffered shared coefficients.
// ---------------------------------------------------------------------------
__global__ void __launch_bounds__(DD, 1) stack_kernel(
    const float* __restrict__ x,
    const float* __restrict__ sp,
    const float* __restrict__ shp,
    const float* __restrict__ latch_init,
    float* __restrict__ out)
{
    __shared__ float4 s_coef[2][NSTK];   // {c, a, e, p}
    __shared__ float2 s_part[2][8];      // per-warp reduction partials {h1, h2}
    __shared__ float  s_g[TT];

    const int b = blockIdx.x;
    const int d = threadIdx.x;
    const int wid = d >> 5, lane = d & 31;

    const float sp_d = sp[d];
    float latch = latch_init[b * DD + d];
    s_g[d] = d_gbuf[b * TT + d];         // TT == DD == 256

    float st[NSTK];
#pragma unroll
    for (int n = 0; n < NSTK; n++) st[n] = ZO;

    const float an_sp = d_norms[0];
    float ptr = 0.f, sharpen = 0.f;
    if (wid == 0) { ptr = (lane == 0) ? 1.f : ZO; sharpen = shp[0]; }

    float xv = x[(size_t)(b * TT) * DD + d];

    // initial pop from latch_init
    {
        float h1 = sp_d * latch, h2 = latch * latch;
#pragma unroll
        for (int o = 16; o; o >>= 1) {
            h1 += __shfl_xor_sync(0xffffffffu, h1, o);
            h2 += __shfl_xor_sync(0xffffffffu, h2, o);
        }
        if (lane == 0) s_part[0][wid] = make_float2(h1, h2);
    }
    __syncthreads();
    float pop;
    {
        float s1 = 0.f, s2 = 0.f;
#pragma unroll
        for (int w = 0; w < 8; w++) { float2 v = s_part[0][w]; s1 += v.x; s2 += v.y; }
        float bn = fmaxf(sqrtf(s2), 1e-8f);
        pop = eluf(s1 / (an_sp * bn));
    }

    int par = 0;
    for (int t = 0; t < TT; t++) {
        par ^= 1;
        int tn = (t + 1 < TT) ? t + 1 : t;
        float xnext = x[((size_t)(b * TT) + tn) * DD + d];

        // latch update for THIS step (g precomputed; pop for this step uses OLD latch)
        float g = s_g[t];
        latch = g * xv + (1.f - g) * latch;

        // partial sums for pop_{t+1}
        float h1 = sp_d * latch, h2 = latch * latch;
#pragma unroll
        for (int o = 16; o; o >>= 1) {
            h1 += __shfl_xor_sync(0xffffffffu, h1, o);
            h2 += __shfl_xor_sync(0xffffffffu, h2, o);
        }
        if (lane == 0) s_part[par][wid] = make_float2(h1, h2);

        float push = 1.f - pop;

        // warp 0: pointer update + sharpen + broadcast coefficients
        if (wid == 0) {
            float pp = __shfl_sync(0xffffffffu, ptr, (lane + 31) & 31); // ptr[n-1]
            float pq = __shfl_sync(0xffffffffu, ptr, (lane + 1) & 31);  // ptr[n+1]
            float a  = push * pp;
            float bb = pop * ptr;
            float c  = 1.f - a - bb;
            float e  = ZO * bb;
            float np = a + pop * pq;                 // push*pp + pop*pq
            float q  = fmaxf(fmaxf(np, 0.f), 1e-12f);
            q = __powf(q, sharpen);
            float qs = q;
#pragma unroll
            for (int o = 16; o; o >>= 1) qs += __shfl_xor_sync(0xffffffffu, qs, o);
            float pn = q / fmaxf(qs, 1e-8f);
            s_coef[par][lane] = make_float4(c, a, e, pn);
            ptr = pn;
        }
        __syncthreads();

        // stack update + read (all in registers, coefficients broadcast from shared)
        float acc = 0.f;
#pragma unroll
        for (int n = 0; n < NSTK; n++) {
            float4 k = s_coef[par][n];
            st[n] = fmaf(k.x, st[n], fmaf(k.y, xv, k.z));
            acc = fmaf(k.w, st[n], acc);
        }
        out[((size_t)(b * TT) + t) * DD + d] = pop * acc;

        // finalize pop for next step (redundant per thread — avoids a 2nd barrier)
        float s1 = 0.f, s2 = 0.f;
#pragma unroll
        for (int w = 0; w < 8; w++) { float2 v = s_part[par][w]; s1 += v.x; s2 += v.y; }
        float bn = fmaxf(sqrtf(s2), 1e-8f);
        pop = eluf(s1 / (an_sp * bn));

        xv = xnext;
    }
}

// ---------------------------------------------------------------------------
extern "C" void kernel_launch(void* const* d_in, const int* in_sizes, int n_in,
                              void* d_out, int out_size) {
    const float* x   = (const float*)d_in[0];  // [128,256,256]
    const float* sp  = (const float*)d_in[1];  // [256]
    const float* shp = (const float*)d_in[2];  // [1]
    const float* le  = (const float*)d_in[3];  // [256]
    const float* li  = (const float*)d_in[4];  // [128,256]
    float* out = (float*)d_out;                // [128,256,256]

    norms_kernel<<<1, 256>>>(sp, le);
    gpass_kernel<<<(BB * TT) / 8, 256>>>(x, le);
    stack_kernel<<<BB, DD>>>(x, sp, shp, li, out);
}